// round 3
// baseline (speedup 1.0000x reference)
#include <cuda_runtime.h>
#include <math_constants.h>

#define NFEAT 65536
#define FD    512
#define NC    256
#define RPC   (NFEAT / NC)      // 256 rows per class
#define F4D   (FD / 4)          // 128 float4 per row
#define RSPLIT 8                // row-chunks per class
#define RCHUNK (RPC / RSPLIT)   // 32 rows per chunk

// Scratch (no cudaMalloc allowed)
__device__ float g_partial[RSPLIT * NC * FD];  // 4 MB partial sums
__device__ float g_centers[NC * FD];           // normalized centers
__device__ float g_rowval[NC];                 // per-row (1 - min_off_diag)
__device__ unsigned int g_cnt[NC];             // per-class fan-in counters (reset by finisher)
__device__ unsigned int g_cnt2;                // sim fan-in counter (reset by finisher)

// ---------------------------------------------------------------------------
// Kernel 1: partial row-sums with per-class fan-in finalize.
// grid = NC*RSPLIT = 2048 blocks, 128 threads. Block b: class c = b>>3,
// chunk s = b&7 (rows [s*32, s*32+32)). Thread t owns float4 column t.
// The last block to finish a class folds the 8 partials, applies mean and
// L2 normalization, writes g_centers[c], and resets the class counter.
// ---------------------------------------------------------------------------
__global__ void __launch_bounds__(128) centers_kernel(const float* __restrict__ feat) {
    const int b = blockIdx.x;
    const int c = b >> 3;
    const int s = b & 7;
    const int t = threadIdx.x;                 // 0..127

    const float4* __restrict__ p =
        reinterpret_cast<const float4*>(feat)
        + ((size_t)c * RPC + (size_t)s * RCHUNK) * F4D + t;

    float4 acc = make_float4(0.f, 0.f, 0.f, 0.f);
    #pragma unroll 8
    for (int r = 0; r < RCHUNK; ++r) {
        float4 v = __ldcs(p + (size_t)r * F4D);
        acc.x += v.x; acc.y += v.y; acc.z += v.z; acc.w += v.w;
    }
    reinterpret_cast<float4*>(g_partial)[((size_t)s * NC + c) * F4D + t] = acc;

    // fan-in: last of the 8 blocks for this class does the finalize
    __threadfence();
    __shared__ unsigned int s_prev;
    if (t == 0) s_prev = atomicAdd(&g_cnt[c], 1u);
    __syncthreads();
    if (s_prev != RSPLIT - 1) return;
    __threadfence();  // acquire: see all partials

    float4 sum = make_float4(0.f, 0.f, 0.f, 0.f);
    #pragma unroll
    for (int k = 0; k < RSPLIT; ++k) {
        const float4* q = reinterpret_cast<const float4*>(g_partial) + ((size_t)k * NC + c) * F4D + t;
        float4 v = __ldcg(q);
        sum.x += v.x; sum.y += v.y; sum.z += v.z; sum.w += v.w;
    }
    const float inv = 1.0f / (float)RPC;
    sum.x *= inv; sum.y *= inv; sum.z *= inv; sum.w *= inv;

    // block-wide sum of squares (deterministic tree reduce)
    float ss = sum.x*sum.x + sum.y*sum.y + sum.z*sum.z + sum.w*sum.w;
    #pragma unroll
    for (int o = 16; o > 0; o >>= 1)
        ss += __shfl_xor_sync(0xffffffffu, ss, o);

    __shared__ float sred[4];
    if ((t & 31) == 0) sred[t >> 5] = ss;
    __syncthreads();
    float total = sred[0] + sred[1] + sred[2] + sred[3];

    float invn = 1.0f / fmaxf(sqrtf(total), 1e-8f);
    float4 o4 = make_float4(sum.x * invn, sum.y * invn, sum.z * invn, sum.w * invn);
    reinterpret_cast<float4*>(g_centers)[(size_t)c * F4D + t] = o4;

    if (t == 0) g_cnt[c] = 0u;   // reset for next graph replay
}

// ---------------------------------------------------------------------------
// Kernel 2: cosine-sim row mins + fan-in final sum.
// grid = NC/4 = 64 blocks, 256 threads. 4 i-rows per block in shared; 8 warps
// each own j = warp, warp+8, ... The last block to finish sums (1 - min) over
// all 256 rows into out[0] and resets the counter.
// ---------------------------------------------------------------------------
__global__ void __launch_bounds__(256) sim_kernel(float* __restrict__ out) {
    const int ib   = blockIdx.x * 4;
    const int t    = threadIdx.x;
    const int w    = t >> 5;
    const int lane = t & 31;

    __shared__ float sc[4 * FD];               // 8 KB
    {
        const float4* src = reinterpret_cast<const float4*>(g_centers + (size_t)ib * FD);
        float4* dst = reinterpret_cast<float4*>(sc);
        for (int k = t; k < 4 * F4D; k += 256) dst[k] = src[k];
    }
    __syncthreads();

    float mn0 = CUDART_INF_F, mn1 = CUDART_INF_F, mn2 = CUDART_INF_F, mn3 = CUDART_INF_F;

    const float4* s0 = reinterpret_cast<const float4*>(sc);
    const float4* s1 = s0 + F4D;
    const float4* s2 = s1 + F4D;
    const float4* s3 = s2 + F4D;

    for (int j = w; j < NC; j += 8) {
        const float4* cj = reinterpret_cast<const float4*>(g_centers + (size_t)j * FD);
        float d0 = 0.f, d1 = 0.f, d2 = 0.f, d3 = 0.f;
        #pragma unroll
        for (int k = 0; k < 4; ++k) {
            int idx = lane + k * 32;
            float4 v  = cj[idx];
            float4 a0 = s0[idx], a1 = s1[idx], a2 = s2[idx], a3 = s3[idx];
            d0 += v.x*a0.x + v.y*a0.y + v.z*a0.z + v.w*a0.w;
            d1 += v.x*a1.x + v.y*a1.y + v.z*a1.z + v.w*a1.w;
            d2 += v.x*a2.x + v.y*a2.y + v.z*a2.z + v.w*a2.w;
            d3 += v.x*a3.x + v.y*a3.y + v.z*a3.z + v.w*a3.w;
        }
        #pragma unroll
        for (int o = 16; o > 0; o >>= 1) {
            d0 += __shfl_xor_sync(0xffffffffu, d0, o);
            d1 += __shfl_xor_sync(0xffffffffu, d1, o);
            d2 += __shfl_xor_sync(0xffffffffu, d2, o);
            d3 += __shfl_xor_sync(0xffffffffu, d3, o);
        }
        if (j != ib + 0) mn0 = fminf(mn0, d0);
        if (j != ib + 1) mn1 = fminf(mn1, d1);
        if (j != ib + 2) mn2 = fminf(mn2, d2);
        if (j != ib + 3) mn3 = fminf(mn3, d3);
    }

    __shared__ float smin[8][4];
    if (lane == 0) {
        smin[w][0] = mn0; smin[w][1] = mn1; smin[w][2] = mn2; smin[w][3] = mn3;
    }
    __syncthreads();
    if (t < 4) {
        float m = CUDART_INF_F;
        #pragma unroll
        for (int ww = 0; ww < 8; ++ww) m = fminf(m, smin[ww][t]);
        g_rowval[ib + t] = 1.0f - m;
    }

    // fan-in: last block sums all 256 row values into out[0]
    __threadfence();
    __shared__ unsigned int s_prev;
    if (t == 0) s_prev = atomicAdd(&g_cnt2, 1u);
    __syncthreads();
    if (s_prev != (NC / 4) - 1) return;
    __threadfence();  // acquire: see all g_rowval

    float v = __ldcg(&g_rowval[t]);
    #pragma unroll
    for (int o = 16; o > 0; o >>= 1)
        v += __shfl_xor_sync(0xffffffffu, v, o);

    __shared__ float sred[8];
    if (lane == 0) sred[w] = v;
    __syncthreads();
    if (t == 0) {
        float total = 0.f;
        #pragma unroll
        for (int i = 0; i < 8; ++i) total += sred[i];
        out[0] = total;
        g_cnt2 = 0u;   // reset for next graph replay
    }
}

extern "C" void kernel_launch(void* const* d_in, const int* in_sizes, int n_in,
                              void* d_out, int out_size) {
    const float* feat = (const float*)d_in[0];
    float* out = (float*)d_out;

    centers_kernel<<<NC * RSPLIT, 128>>>(feat);
    sim_kernel<<<NC / 4, 256>>>(out);
}

// round 4
// speedup vs baseline: 1.2778x; 1.2778x over previous
#include <cuda_runtime.h>
#include <math_constants.h>

#define NFEAT 65536
#define FD    512
#define NC    256
#define RPC   (NFEAT / NC)      // 256 rows per class
#define F4D   (FD / 4)          // 128 float4 per row
#define RSPLIT 4                // row-chunks per class
#define RCHUNK (RPC / RSPLIT)   // 64 rows per chunk

// Scratch (no cudaMalloc allowed)
__device__ float g_partial[RSPLIT * NC * FD];  // 2 MB partial sums
__device__ float g_centers[NC * FD];           // normalized centers, row-major [j][k]
__device__ float g_centersT[FD * NC];          // normalized centers, transposed [k][j]
__device__ float g_rowval[NC];                 // per-row (1 - min_off_diag)
__device__ unsigned int g_cnt[NC];             // per-class fan-in counters
__device__ unsigned int g_cnt2;                // sim fan-in counter

// ---------------------------------------------------------------------------
// Kernel 1: partial row-sums + per-class fan-in finalize (mean, L2-norm,
// write both row-major and transposed layouts).
// grid = NC*RSPLIT = 1024, block = 128. Block b: class c=b>>2, chunk s=b&3.
// ---------------------------------------------------------------------------
__global__ void __launch_bounds__(128) centers_kernel(const float* __restrict__ feat) {
    const int b = blockIdx.x;
    const int c = b >> 2;
    const int s = b & 3;
    const int t = threadIdx.x;                 // 0..127

    const float4* __restrict__ p =
        reinterpret_cast<const float4*>(feat)
        + ((size_t)c * RPC + (size_t)s * RCHUNK) * F4D + t;

    float4 acc = make_float4(0.f, 0.f, 0.f, 0.f);
    #pragma unroll 8
    for (int r = 0; r < RCHUNK; ++r) {
        float4 v = __ldcs(p + (size_t)r * F4D);
        acc.x += v.x; acc.y += v.y; acc.z += v.z; acc.w += v.w;
    }
    reinterpret_cast<float4*>(g_partial)[((size_t)s * NC + c) * F4D + t] = acc;

    // fan-in: last of the 4 blocks for this class finalizes
    __threadfence();
    __shared__ unsigned int s_prev;
    if (t == 0) s_prev = atomicAdd(&g_cnt[c], 1u);
    __syncthreads();
    if (s_prev != RSPLIT - 1) return;
    __threadfence();

    float4 sum = make_float4(0.f, 0.f, 0.f, 0.f);
    #pragma unroll
    for (int k = 0; k < RSPLIT; ++k) {
        const float4* q = reinterpret_cast<const float4*>(g_partial) + ((size_t)k * NC + c) * F4D + t;
        float4 v = __ldcg(q);
        sum.x += v.x; sum.y += v.y; sum.z += v.z; sum.w += v.w;
    }
    const float inv = 1.0f / (float)RPC;
    sum.x *= inv; sum.y *= inv; sum.z *= inv; sum.w *= inv;

    float ss = sum.x*sum.x + sum.y*sum.y + sum.z*sum.z + sum.w*sum.w;
    #pragma unroll
    for (int o = 16; o > 0; o >>= 1)
        ss += __shfl_xor_sync(0xffffffffu, ss, o);

    __shared__ float sred[4];
    if ((t & 31) == 0) sred[t >> 5] = ss;
    __syncthreads();
    float total = sred[0] + sred[1] + sred[2] + sred[3];
    float invn = 1.0f / fmaxf(sqrtf(total), 1e-8f);

    float4 o4 = make_float4(sum.x * invn, sum.y * invn, sum.z * invn, sum.w * invn);
    reinterpret_cast<float4*>(g_centers)[(size_t)c * F4D + t] = o4;

    // transposed writes: CT[k][c], k = 4t..4t+3 (scattered, small)
    g_centersT[(size_t)(4 * t + 0) * NC + c] = o4.x;
    g_centersT[(size_t)(4 * t + 1) * NC + c] = o4.y;
    g_centersT[(size_t)(4 * t + 2) * NC + c] = o4.z;
    g_centersT[(size_t)(4 * t + 3) * NC + c] = o4.w;

    if (t == 0) g_cnt[c] = 0u;   // reset for next graph replay
}

// ---------------------------------------------------------------------------
// Kernel 2: sim row mins via transposed register-tiled product + fan-in sum.
// grid = NC/4 = 64 blocks (4 i-rows each), 256 threads.
// Thread t: jq = t&63 owns j = 4*jq..4*jq+3 (float4 from CT, coalesced),
//           ks = t>>6 owns k-slice [ks*128, ks*128+128).
// 16 accumulators/thread; i-row values broadcast from shared (conflict-free).
// ---------------------------------------------------------------------------
__global__ void __launch_bounds__(256) sim_kernel(float* __restrict__ out) {
    const int ib = blockIdx.x * 4;             // i rows [ib, ib+4)
    const int t  = threadIdx.x;
    const int jq = t & 63;
    const int ks = t >> 6;

    __shared__ float4 sc4[4][F4D];             // 8 KB: i-rows, k-major float4
    __shared__ float4 red4[256 * 4];           // 16 KB: per-thread partials
    {
        const float4* src = reinterpret_cast<const float4*>(g_centers + (size_t)ib * FD);
        for (int k = t; k < 4 * F4D; k += 256)
            sc4[k >> 7][k & 127] = src[k];
    }
    __syncthreads();

    const float4* __restrict__ ct = reinterpret_cast<const float4*>(g_centersT);

    float acc[4][4];
    #pragma unroll
    for (int i = 0; i < 4; ++i)
        #pragma unroll
        for (int ccc = 0; ccc < 4; ++ccc) acc[i][ccc] = 0.f;

    const int k0base = ks * 128;
    #pragma unroll 4
    for (int kk = 0; kk < 128; kk += 4) {
        const int k = k0base + kk;
        float4 v0 = ct[(size_t)(k + 0) * (NC / 4) + jq];
        float4 v1 = ct[(size_t)(k + 1) * (NC / 4) + jq];
        float4 v2 = ct[(size_t)(k + 2) * (NC / 4) + jq];
        float4 v3 = ct[(size_t)(k + 3) * (NC / 4) + jq];
        #pragma unroll
        for (int i = 0; i < 4; ++i) {
            float4 a = sc4[i][k >> 2];         // broadcast LDS.128
            acc[i][0] += a.x * v0.x + a.y * v1.x + a.z * v2.x + a.w * v3.x;
            acc[i][1] += a.x * v0.y + a.y * v1.y + a.z * v2.y + a.w * v3.y;
            acc[i][2] += a.x * v0.z + a.y * v1.z + a.z * v2.z + a.w * v3.z;
            acc[i][3] += a.x * v0.w + a.y * v1.w + a.z * v2.w + a.w * v3.w;
        }
    }

    // stash partials, fold across the 4 k-slices
    #pragma unroll
    for (int i = 0; i < 4; ++i)
        red4[(size_t)t * 4 + i] = make_float4(acc[i][0], acc[i][1], acc[i][2], acc[i][3]);
    __syncthreads();

    __shared__ float s_minw[2][4];
    if (t < 64) {                              // warps 0 and 1, jq == t
        float mn[4];
        #pragma unroll
        for (int i = 0; i < 4; ++i) {
            float4 a = red4[(size_t)(0 * 64 + t) * 4 + i];
            float4 b = red4[(size_t)(1 * 64 + t) * 4 + i];
            float4 cc = red4[(size_t)(2 * 64 + t) * 4 + i];
            float4 d = red4[(size_t)(3 * 64 + t) * 4 + i];
            float sx = a.x + b.x + cc.x + d.x;
            float sy = a.y + b.y + cc.y + d.y;
            float sz = a.z + b.z + cc.z + d.z;
            float sw = a.w + b.w + cc.w + d.w;
            const int ig = ib + i;
            float m = CUDART_INF_F;
            if (4 * t + 0 != ig) m = fminf(m, sx);
            if (4 * t + 1 != ig) m = fminf(m, sy);
            if (4 * t + 2 != ig) m = fminf(m, sz);
            if (4 * t + 3 != ig) m = fminf(m, sw);
            mn[i] = m;
        }
        #pragma unroll
        for (int o = 16; o > 0; o >>= 1) {
            #pragma unroll
            for (int i = 0; i < 4; ++i)
                mn[i] = fminf(mn[i], __shfl_xor_sync(0xffffffffu, mn[i], o));
        }
        if ((t & 31) == 0) {
            #pragma unroll
            for (int i = 0; i < 4; ++i) s_minw[t >> 5][i] = mn[i];
        }
    }
    __syncthreads();
    if (t < 4)
        g_rowval[ib + t] = 1.0f - fminf(s_minw[0][t], s_minw[1][t]);

    // fan-in: last block sums all 256 row values into out[0]
    __threadfence();
    __shared__ unsigned int s_prev;
    if (t == 0) s_prev = atomicAdd(&g_cnt2, 1u);
    __syncthreads();
    if (s_prev != (NC / 4) - 1) return;
    __threadfence();

    float v = __ldcg(&g_rowval[t]);
    #pragma unroll
    for (int o = 16; o > 0; o >>= 1)
        v += __shfl_xor_sync(0xffffffffu, v, o);

    __shared__ float sfin[8];
    if ((t & 31) == 0) sfin[t >> 5] = v;
    __syncthreads();
    if (t == 0) {
        float total = 0.f;
        #pragma unroll
        for (int i = 0; i < 8; ++i) total += sfin[i];
        out[0] = total;
        g_cnt2 = 0u;   // reset for next graph replay
    }
}

extern "C" void kernel_launch(void* const* d_in, const int* in_sizes, int n_in,
                              void* d_out, int out_size) {
    const float* feat = (const float*)d_in[0];
    float* out = (float*)d_out;

    centers_kernel<<<NC * RSPLIT, 128>>>(feat);
    sim_kernel<<<NC / 4, 256>>>(out);
}

// round 5
// speedup vs baseline: 1.3760x; 1.0769x over previous
#include <cuda_runtime.h>
#include <math_constants.h>

#define NFEAT 65536
#define FD    512
#define NC    256
#define RPC   (NFEAT / NC)      // 256 rows per class
#define F4D   (FD / 4)          // 128 float4 per row
#define RSPLIT 4                // row-chunks per class
#define RCHUNK (RPC / RSPLIT)   // 64 rows per chunk

// Scratch (no cudaMalloc allowed)
__device__ float g_partial[RSPLIT * NC * FD];  // 2 MB partial sums
__device__ float g_centers[NC * FD];           // normalized centers, row-major [j][k]
__device__ float g_centersT[FD * NC];          // normalized centers, transposed [k][j]
__device__ float g_rowval[NC];                 // per-row (1 - min_off_diag)
__device__ unsigned int g_cnt2;                // sim fan-in counter

// ---------------------------------------------------------------------------
// Kernel 1a: partial row-sums. grid = NC*RSPLIT = 1024 blocks, 128 threads.
// Block b: class c = b>>2, chunk s = b&3. Streaming __ldcs, fully coalesced.
// ---------------------------------------------------------------------------
__global__ void __launch_bounds__(128) centers_partial_kernel(const float* __restrict__ feat) {
    const int b = blockIdx.x;
    const int c = b >> 2;
    const int s = b & 3;
    const int t = threadIdx.x;                 // 0..127

    const float4* __restrict__ p =
        reinterpret_cast<const float4*>(feat)
        + ((size_t)c * RPC + (size_t)s * RCHUNK) * F4D + t;

    float4 acc = make_float4(0.f, 0.f, 0.f, 0.f);
    #pragma unroll 8
    for (int r = 0; r < RCHUNK; ++r) {
        float4 v = __ldcs(p + (size_t)r * F4D);
        acc.x += v.x; acc.y += v.y; acc.z += v.z; acc.w += v.w;
    }
    reinterpret_cast<float4*>(g_partial)[((size_t)s * NC + c) * F4D + t] = acc;
}

// ---------------------------------------------------------------------------
// Kernel 1b: fold partials, mean, L2-norm; write row-major + transposed.
// grid = 256, block = 128.
// ---------------------------------------------------------------------------
__global__ void __launch_bounds__(128) centers_finalize_kernel() {
    const int c = blockIdx.x;
    const int t = threadIdx.x;

    float4 sum = make_float4(0.f, 0.f, 0.f, 0.f);
    #pragma unroll
    for (int k = 0; k < RSPLIT; ++k) {
        float4 v = reinterpret_cast<const float4*>(g_partial)[((size_t)k * NC + c) * F4D + t];
        sum.x += v.x; sum.y += v.y; sum.z += v.z; sum.w += v.w;
    }
    const float inv = 1.0f / (float)RPC;
    sum.x *= inv; sum.y *= inv; sum.z *= inv; sum.w *= inv;

    float ss = sum.x*sum.x + sum.y*sum.y + sum.z*sum.z + sum.w*sum.w;
    #pragma unroll
    for (int o = 16; o > 0; o >>= 1)
        ss += __shfl_xor_sync(0xffffffffu, ss, o);

    __shared__ float sred[4];
    if ((t & 31) == 0) sred[t >> 5] = ss;
    __syncthreads();
    float total = sred[0] + sred[1] + sred[2] + sred[3];
    float invn = 1.0f / fmaxf(sqrtf(total), 1e-8f);

    float4 o4 = make_float4(sum.x * invn, sum.y * invn, sum.z * invn, sum.w * invn);
    reinterpret_cast<float4*>(g_centers)[(size_t)c * F4D + t] = o4;

    g_centersT[(size_t)(4 * t + 0) * NC + c] = o4.x;
    g_centersT[(size_t)(4 * t + 1) * NC + c] = o4.y;
    g_centersT[(size_t)(4 * t + 2) * NC + c] = o4.z;
    g_centersT[(size_t)(4 * t + 3) * NC + c] = o4.w;
}

// ---------------------------------------------------------------------------
// Kernel 2: sim row mins, register double-buffered CT loads + fan-in sum.
// grid = 64 (4 i-rows each), block = 256.
// Thread: jq = t&63 owns j = 4jq..4jq+3; ks = t>>6 owns k in [128ks,128ks+128).
// Main loop: 16 chunks of 8 k's; prefetch next chunk's 8 independent LDG.128
// before computing current chunk (128 FMA) -> load latency fully hidden.
// ---------------------------------------------------------------------------
#define SIM_STEP(AV0, AV1, AV2, AV3, V)                                      \
    acc[0][0] += (AV0)*(V).x; acc[0][1] += (AV0)*(V).y;                      \
    acc[0][2] += (AV0)*(V).z; acc[0][3] += (AV0)*(V).w;                      \
    acc[1][0] += (AV1)*(V).x; acc[1][1] += (AV1)*(V).y;                      \
    acc[1][2] += (AV1)*(V).z; acc[1][3] += (AV1)*(V).w;                      \
    acc[2][0] += (AV2)*(V).x; acc[2][1] += (AV2)*(V).y;                      \
    acc[2][2] += (AV2)*(V).z; acc[2][3] += (AV2)*(V).w;                      \
    acc[3][0] += (AV3)*(V).x; acc[3][1] += (AV3)*(V).y;                      \
    acc[3][2] += (AV3)*(V).z; acc[3][3] += (AV3)*(V).w;

__global__ void __launch_bounds__(256) sim_kernel(float* __restrict__ out) {
    const int ib = blockIdx.x * 4;             // i rows [ib, ib+4)
    const int t  = threadIdx.x;
    const int jq = t & 63;
    const int ks = t >> 6;

    __shared__ float4 sc4[4][F4D];             // 8 KB: i-rows
    __shared__ float4 red4[256 * 4];           // 16 KB: per-thread partials
    {
        const float4* src = reinterpret_cast<const float4*>(g_centers + (size_t)ib * FD);
        for (int k = t; k < 4 * F4D; k += 256)
            sc4[k >> 7][k & 127] = src[k];
    }
    __syncthreads();

    const float4* __restrict__ ct = reinterpret_cast<const float4*>(g_centersT);

    float acc[4][4];
    #pragma unroll
    for (int i = 0; i < 4; ++i)
        #pragma unroll
        for (int j = 0; j < 4; ++j) acc[i][j] = 0.f;

    const int kb = ks * 128;
    float4 buf[2][8];
    #pragma unroll
    for (int u = 0; u < 8; ++u)
        buf[0][u] = __ldcg(&ct[(size_t)(kb + u) * (NC / 4) + jq]);

    #pragma unroll 2
    for (int ch = 0; ch < 16; ++ch) {
        const int pb = ch & 1;
        if (ch < 15) {
            const int k2 = kb + (ch + 1) * 8;
            #pragma unroll
            for (int u = 0; u < 8; ++u)
                buf[pb ^ 1][u] = __ldcg(&ct[(size_t)(k2 + u) * (NC / 4) + jq]);
        }
        const int kf0 = (kb + ch * 8) >> 2;    // float4-k index
        #pragma unroll
        for (int g = 0; g < 2; ++g) {
            const int kf = kf0 + g;
            float4 a0 = sc4[0][kf];
            float4 a1 = sc4[1][kf];
            float4 a2 = sc4[2][kf];
            float4 a3 = sc4[3][kf];
            SIM_STEP(a0.x, a1.x, a2.x, a3.x, buf[pb][g * 4 + 0]);
            SIM_STEP(a0.y, a1.y, a2.y, a3.y, buf[pb][g * 4 + 1]);
            SIM_STEP(a0.z, a1.z, a2.z, a3.z, buf[pb][g * 4 + 2]);
            SIM_STEP(a0.w, a1.w, a2.w, a3.w, buf[pb][g * 4 + 3]);
        }
    }

    // stash partials, fold across the 4 k-slices
    #pragma unroll
    for (int i = 0; i < 4; ++i)
        red4[(size_t)t * 4 + i] = make_float4(acc[i][0], acc[i][1], acc[i][2], acc[i][3]);
    __syncthreads();

    __shared__ float s_minw[2][4];
    if (t < 64) {                              // jq == t
        float mn[4];
        #pragma unroll
        for (int i = 0; i < 4; ++i) {
            float4 a = red4[(size_t)(0 * 64 + t) * 4 + i];
            float4 b = red4[(size_t)(1 * 64 + t) * 4 + i];
            float4 cc = red4[(size_t)(2 * 64 + t) * 4 + i];
            float4 d = red4[(size_t)(3 * 64 + t) * 4 + i];
            float sx = a.x + b.x + cc.x + d.x;
            float sy = a.y + b.y + cc.y + d.y;
            float sz = a.z + b.z + cc.z + d.z;
            float sw = a.w + b.w + cc.w + d.w;
            const int ig = ib + i;
            float m = CUDART_INF_F;
            if (4 * t + 0 != ig) m = fminf(m, sx);
            if (4 * t + 1 != ig) m = fminf(m, sy);
            if (4 * t + 2 != ig) m = fminf(m, sz);
            if (4 * t + 3 != ig) m = fminf(m, sw);
            mn[i] = m;
        }
        #pragma unroll
        for (int o = 16; o > 0; o >>= 1) {
            #pragma unroll
            for (int i = 0; i < 4; ++i)
                mn[i] = fminf(mn[i], __shfl_xor_sync(0xffffffffu, mn[i], o));
        }
        if ((t & 31) == 0) {
            #pragma unroll
            for (int i = 0; i < 4; ++i) s_minw[t >> 5][i] = mn[i];
        }
    }
    __syncthreads();
    if (t < 4)
        g_rowval[ib + t] = 1.0f - fminf(s_minw[0][t], s_minw[1][t]);

    // fan-in: last block sums all 256 row values into out[0]
    __threadfence();
    __shared__ unsigned int s_prev;
    if (t == 0) s_prev = atomicAdd(&g_cnt2, 1u);
    __syncthreads();
    if (s_prev != (NC / 4) - 1) return;
    __threadfence();

    float v = __ldcg(&g_rowval[t]);
    #pragma unroll
    for (int o = 16; o > 0; o >>= 1)
        v += __shfl_xor_sync(0xffffffffu, v, o);

    __shared__ float sfin[8];
    if ((t & 31) == 0) sfin[t >> 5] = v;
    __syncthreads();
    if (t == 0) {
        float total = 0.f;
        #pragma unroll
        for (int i = 0; i < 8; ++i) total += sfin[i];
        out[0] = total;
        g_cnt2 = 0u;   // reset for next graph replay
    }
}

extern "C" void kernel_launch(void* const* d_in, const int* in_sizes, int n_in,
                              void* d_out, int out_size) {
    const float* feat = (const float*)d_in[0];
    float* out = (float*)d_out;

    centers_partial_kernel<<<NC * RSPLIT, 128>>>(feat);
    centers_finalize_kernel<<<NC, 128>>>();
    sim_kernel<<<NC / 4, 256>>>(out);
}